// round 12
// baseline (speedup 1.0000x reference)
#include <cuda_runtime.h>
#include <cuda_fp16.h>
#include <stdint.h>

#define VOCAB 100000
#define EMBED 64
#define KIDS  20
#define BROWS (1024 * 50)          // B*S output rows = 51200

// Wt in fp16, [V, E]: each vocab row = 64 halves = 128 B = ONE L2 line.
// 12.8 MB — L2-resident (126 MB L2).
__device__ __half g_Wt[VOCAB * EMBED];

// ---------------------------------------------------------------------------
// Kernel 1: transpose + downconvert  W[E,V] f32 -> Wt[V,E] f16  (unchanged,
// proven at ~5 us; kept identical for clean attribution)
// ---------------------------------------------------------------------------
__global__ __launch_bounds__(256)
void transpose_W_kernel(const float* __restrict__ W) {
    __shared__ float tile[EMBED][33];          // [e][v], +1 pad
    const int v0  = blockIdx.x * 32;
    const int tid = threadIdx.x;

    #pragma unroll
    for (int r = 0; r < 2; r++) {
        const int idx = tid + r * 256;         // 0..511
        const int e   = idx >> 3;              // 0..63
        const int c   = idx & 7;               // float4 col 0..7
        const float4 f = __ldg(reinterpret_cast<const float4*>(
            W + (size_t)e * VOCAB + v0) + c);
        tile[e][4 * c]     = f.x;
        tile[e][4 * c + 1] = f.y;
        tile[e][4 * c + 2] = f.z;
        tile[e][4 * c + 3] = f.w;
    }
    __syncthreads();

    __half2* WtH2 = reinterpret_cast<__half2*>(g_Wt);
    #pragma unroll
    for (int r = 0; r < 4; r++) {
        const int idx  = tid + r * 256;
        const int vrow = idx >> 5;             // 0..31 (constant per warp)
        const int c    = idx & 31;             // half2 col 0..31
        const float2 f = make_float2(tile[2 * c][vrow], tile[2 * c + 1][vrow]);
        WtH2[(size_t)(v0 + vrow) * (EMBED / 2) + c] = __float22half2_rn(f);
    }
}

// ---------------------------------------------------------------------------
// Kernel 2: gather-reduce, exactly one FULL wave.
// Grid = 148 SMs x 8 CTAs = 1184 blocks x 256 threads (100% occupancy,
// no second wave). Work balanced: first 288 blocks take 44 rows, rest 43
// (288*44 + 896*43 = 51200). 8 lanes per row; each group loops 1-2 rows;
// 20 independent LDG.128 per row; fp32 accumulation.
// ---------------------------------------------------------------------------
#define GBLOCKS 1184               // 148 * 8
#define THREADS 256
#define ROWS_BASE  43              // 51200 / 1184
#define ROWS_EXTRA 288             // 51200 % 1184

__global__ __launch_bounds__(THREADS, 8)
void gather_reduce_kernel(const int* __restrict__ ids,
                          const float* __restrict__ bias,
                          float* __restrict__ out) {
    const int b     = blockIdx.x;
    const int extra = (b < ROWS_EXTRA);
    const int row_start = ROWS_BASE * b + min(b, ROWS_EXTRA);
    const int nrows     = ROWS_BASE + extra;   // 43 or 44

    const int group = threadIdx.x >> 3;        // 0..31
    const int lane  = threadIdx.x & 7;         // owns e in [8*lane, 8*lane+8)

    // Bias: 8 floats per lane, loop-invariant (L1-resident broadcast).
    const float4 b0 = __ldg(reinterpret_cast<const float4*>(bias) + 2 * lane);
    const float4 b1 = __ldg(reinterpret_cast<const float4*>(bias) + 2 * lane + 1);

    const float4* WtV = reinterpret_cast<const float4*>(g_Wt);  // 16B = 8 halves

    #pragma unroll 1
    for (int r = group; r < nrows; r += 32) {
        const size_t row = (size_t)row_start + r;
        const int* idp = ids + row * KIDS;

        int id[KIDS];
        #pragma unroll
        for (int k = 0; k < KIDS; k++) id[k] = __ldg(idp + k);

        float acc[8] = { b0.x, b0.y, b0.z, b0.w, b1.x, b1.y, b1.z, b1.w };

        #pragma unroll
        for (int k = 0; k < KIDS; k++) {
            const float4 raw = __ldg(&WtV[(size_t)id[k] * 8 + lane]);
            const __half2* h = reinterpret_cast<const __half2*>(&raw);
            #pragma unroll
            for (int p = 0; p < 4; p++) {
                const float2 f = __half22float2(h[p]);
                acc[2 * p]     += f.x;
                acc[2 * p + 1] += f.y;
            }
        }

        float4* o = reinterpret_cast<float4*>(out + row * EMBED + lane * 8);
        o[0] = make_float4(acc[0], acc[1], acc[2], acc[3]);
        o[1] = make_float4(acc[4], acc[5], acc[6], acc[7]);
    }
}

// ---------------------------------------------------------------------------
// Launch: inputs in metadata order: content_input (int32), W (f32), b (f32)
// ---------------------------------------------------------------------------
extern "C" void kernel_launch(void* const* d_in, const int* in_sizes, int n_in,
                              void* d_out, int out_size) {
    const int*   ids  = (const int*)  d_in[0];   // [B, S, K] int32
    const float* W    = (const float*)d_in[1];   // [E, V] f32
    const float* bias = (const float*)d_in[2];   // [E] f32
    float*       out  = (float*)d_out;           // [B, S, E] f32

    transpose_W_kernel<<<VOCAB / 32, 256>>>(W);  // 3125 blocks

    gather_reduce_kernel<<<GBLOCKS, THREADS>>>(ids, bias, out);
}

// round 15
// speedup vs baseline: 2.4137x; 2.4137x over previous
#include <cuda_runtime.h>
#include <cuda_fp16.h>
#include <stdint.h>

#define VOCAB 100000
#define EMBED 64
#define KIDS  20
#define BROWS (1024 * 50)          // B*S output rows = 51200

// Wt in fp16, [V, E]: each vocab row = 64 halves = 128 B = ONE L2 line.
// 12.8 MB — L2-resident (126 MB L2).
__device__ __half g_Wt[VOCAB * EMBED];

// ---------------------------------------------------------------------------
// Kernel 1: transpose + downconvert  W[E,V] f32 -> Wt[V,E] f16
// Tile = 64 v x 64 e. Grid = ceil(V/64) = 1563, block = 256.
// Read:  1024 float4 per tile, 4 independent LDG.128 per thread (MLP=4).
// Write: 2048 half2 per tile; each warp stores one full 128B Wt vocab row.
// Last block (vrem=32) guarded.
// ---------------------------------------------------------------------------
__global__ __launch_bounds__(256)
void transpose_W_kernel(const float* __restrict__ W) {
    __shared__ float tile[EMBED][65];          // [e][v], +1 pad
    const int v0   = blockIdx.x * 64;
    const int tid  = threadIdx.x;
    const int vrem = VOCAB - v0;               // 64, except 32 for last block

    // Read: 64 e-rows x 16 float4 = 1024 float4; 4 per thread, coalesced.
    #pragma unroll
    for (int r = 0; r < 4; r++) {
        const int idx = tid + r * 256;         // 0..1023
        const int e   = idx >> 4;              // 0..63
        const int c   = idx & 15;              // float4 col 0..15
        const int v   = c * 4;
        if (v < vrem) {                        // vrem is a multiple of 4
            const float4 f = __ldg(reinterpret_cast<const float4*>(
                W + (size_t)e * VOCAB + v0) + c);
            tile[e][v]     = f.x;
            tile[e][v + 1] = f.y;
            tile[e][v + 2] = f.z;
            tile[e][v + 3] = f.w;
        }
    }
    __syncthreads();

    // Write: 64 vrows x 32 half2 = 2048 half2; warp = one full 128B vrow.
    __half2* WtH2 = reinterpret_cast<__half2*>(g_Wt);
    #pragma unroll
    for (int r = 0; r < 8; r++) {
        const int idx  = tid + r * 256;
        const int vrow = idx >> 5;             // 0..63 (constant per warp)
        const int c    = idx & 31;             // half2 col 0..31
        if (vrow < vrem) {
            const float2 f = make_float2(tile[2 * c][vrow], tile[2 * c + 1][vrow]);
            WtH2[(size_t)(v0 + vrow) * (EMBED / 2) + c] = __float22half2_rn(f);
        }
    }
}

// ---------------------------------------------------------------------------
// Kernel 2: gather-reduce — EXACT R9/Round-10 proven shape (14.0 us).
// 8 lanes per row (lane owns 8 embeds = 16 B of the 128 B row), 32 rows per
// 256-thread block, smem id staging, 20 independent LDG.128 per thread,
// fp32 accumulation. __launch_bounds__(256, 8) pins regs at 32.
// ---------------------------------------------------------------------------
#define ROWS_PER_BLOCK 32
#define THREADS 256

__global__ __launch_bounds__(THREADS, 8)
void gather_reduce_kernel(const int* __restrict__ ids,
                          const float* __restrict__ bias,
                          float* __restrict__ out) {
    __shared__ int s_ids[ROWS_PER_BLOCK * KIDS];   // 640 ints

    const int tid = threadIdx.x;
    const size_t block_id_base = (size_t)blockIdx.x * (ROWS_PER_BLOCK * KIDS);

    // Coalesced stage of this block's 640 ids.
    #pragma unroll
    for (int i = tid; i < ROWS_PER_BLOCK * KIDS; i += THREADS) {
        s_ids[i] = __ldg(ids + block_id_base + i);
    }

    const int row_local = tid >> 3;     // 0..31
    const int lane      = tid & 7;      // 0..7, owns e in [8*lane, 8*lane+8)

    // Bias: 8 floats per lane, broadcast across rows (L1-resident).
    const float4 b0 = __ldg(reinterpret_cast<const float4*>(bias) + 2 * lane);
    const float4 b1 = __ldg(reinterpret_cast<const float4*>(bias) + 2 * lane + 1);
    float acc[8] = { b0.x, b0.y, b0.z, b0.w, b1.x, b1.y, b1.z, b1.w };

    __syncthreads();

    int id[KIDS];
    #pragma unroll
    for (int k = 0; k < KIDS; k++) id[k] = s_ids[row_local * KIDS + k];

    const float4* WtV = reinterpret_cast<const float4*>(g_Wt);  // 16B = 8 halves

    #pragma unroll
    for (int k = 0; k < KIDS; k++) {
        const float4 raw = __ldg(&WtV[(size_t)id[k] * 8 + lane]);
        const __half2* h = reinterpret_cast<const __half2*>(&raw);
        #pragma unroll
        for (int p = 0; p < 4; p++) {
            const float2 f = __half22float2(h[p]);
            acc[2 * p]     += f.x;
            acc[2 * p + 1] += f.y;
        }
    }

    // Output: lane writes 32 B; warp's 4 rows = 512 B contiguous.
    const size_t row = (size_t)blockIdx.x * ROWS_PER_BLOCK + row_local;
    float4* o = reinterpret_cast<float4*>(out + row * EMBED + lane * 8);
    o[0] = make_float4(acc[0], acc[1], acc[2], acc[3]);
    o[1] = make_float4(acc[4], acc[5], acc[6], acc[7]);
}

// ---------------------------------------------------------------------------
// Launch: inputs in metadata order: content_input (int32), W (f32), b (f32)
// ---------------------------------------------------------------------------
extern "C" void kernel_launch(void* const* d_in, const int* in_sizes, int n_in,
                              void* d_out, int out_size) {
    const int*   ids  = (const int*)  d_in[0];   // [B, S, K] int32
    const float* W    = (const float*)d_in[1];   // [E, V] f32
    const float* bias = (const float*)d_in[2];   // [E] f32
    float*       out  = (float*)d_out;           // [B, S, E] f32

    const int tblocks = (VOCAB + 63) / 64;       // 1563
    transpose_W_kernel<<<tblocks, 256>>>(W);

    const int blocks = BROWS / ROWS_PER_BLOCK;   // 1600
    gather_reduce_kernel<<<blocks, THREADS>>>(ids, bias, out);
}

// round 16
// speedup vs baseline: 2.5824x; 1.0699x over previous
#include <cuda_runtime.h>
#include <cuda_fp16.h>
#include <stdint.h>

#define VOCAB 100000
#define EMBED 64
#define KIDS  20
#define BROWS (1024 * 50)          // B*S output rows = 51200

// Wt in fp16, [V, E]: each vocab row = 64 halves = 128 B = ONE L2 line.
// 12.8 MB — L2-resident (126 MB L2).
__device__ __half g_Wt[VOCAB * EMBED];

// ---------------------------------------------------------------------------
// Kernel 1: transpose + downconvert  W[E,V] f32 -> Wt[V,E] f16
// Tile = 32 v x 64 e (proven shape), block = 128 threads, grid = 3125.
// Read:  512 float4 per tile = 4 independent LDG.128 per thread (MLP=4).
// Write: 1024 half2 per tile, 8 per thread; warp = one contiguous 128B vrow.
// No guards: 3125 * 32 = 100000 exactly.
// ---------------------------------------------------------------------------
__global__ __launch_bounds__(128)
void transpose_W_kernel(const float* __restrict__ W) {
    __shared__ float tile[EMBED][33];          // [e][v], +1 pad (8.4 KB)
    const int v0  = blockIdx.x * 32;
    const int tid = threadIdx.x;               // 0..127

    // Read: 64 e-rows x 8 float4 = 512 float4; 4 per thread, coalesced.
    #pragma unroll
    for (int r = 0; r < 4; r++) {
        const int idx = tid + r * 128;         // 0..511
        const int e   = idx >> 3;              // 0..63
        const int c   = idx & 7;               // float4 col 0..7
        const float4 f = __ldg(reinterpret_cast<const float4*>(
            W + (size_t)e * VOCAB + v0) + c);
        tile[e][4 * c]     = f.x;
        tile[e][4 * c + 1] = f.y;
        tile[e][4 * c + 2] = f.z;
        tile[e][4 * c + 3] = f.w;
    }
    __syncthreads();

    // Write: 32 vrows x 32 half2 = 1024 half2; warp = one full 128B vrow.
    __half2* WtH2 = reinterpret_cast<__half2*>(g_Wt);
    #pragma unroll
    for (int r = 0; r < 8; r++) {
        const int idx  = tid + r * 128;
        const int vrow = idx >> 5;             // 0..31 (constant per warp)
        const int c    = idx & 31;             // half2 col 0..31
        const float2 f = make_float2(tile[2 * c][vrow], tile[2 * c + 1][vrow]);
        WtH2[(size_t)(v0 + vrow) * (EMBED / 2) + c] = __float22half2_rn(f);
    }
}

// ---------------------------------------------------------------------------
// Kernel 2: gather-reduce — EXACT R9 proven shape (14.0 us). Do not touch.
// 8 lanes per row, 32 rows per 256-thread block, smem id staging,
// 20 independent LDG.128 per thread, fp32 accumulation, 32 regs.
// ---------------------------------------------------------------------------
#define ROWS_PER_BLOCK 32
#define THREADS 256

__global__ __launch_bounds__(THREADS, 8)
void gather_reduce_kernel(const int* __restrict__ ids,
                          const float* __restrict__ bias,
                          float* __restrict__ out) {
    __shared__ int s_ids[ROWS_PER_BLOCK * KIDS];   // 640 ints

    const int tid = threadIdx.x;
    const size_t block_id_base = (size_t)blockIdx.x * (ROWS_PER_BLOCK * KIDS);

    #pragma unroll
    for (int i = tid; i < ROWS_PER_BLOCK * KIDS; i += THREADS) {
        s_ids[i] = __ldg(ids + block_id_base + i);
    }

    const int row_local = tid >> 3;     // 0..31
    const int lane      = tid & 7;      // 0..7, owns e in [8*lane, 8*lane+8)

    const float4 b0 = __ldg(reinterpret_cast<const float4*>(bias) + 2 * lane);
    const float4 b1 = __ldg(reinterpret_cast<const float4*>(bias) + 2 * lane + 1);
    float acc[8] = { b0.x, b0.y, b0.z, b0.w, b1.x, b1.y, b1.z, b1.w };

    __syncthreads();

    int id[KIDS];
    #pragma unroll
    for (int k = 0; k < KIDS; k++) id[k] = s_ids[row_local * KIDS + k];

    const float4* WtV = reinterpret_cast<const float4*>(g_Wt);  // 16B = 8 halves

    #pragma unroll
    for (int k = 0; k < KIDS; k++) {
        const float4 raw = __ldg(&WtV[(size_t)id[k] * 8 + lane]);
        const __half2* h = reinterpret_cast<const __half2*>(&raw);
        #pragma unroll
        for (int p = 0; p < 4; p++) {
            const float2 f = __half22float2(h[p]);
            acc[2 * p]     += f.x;
            acc[2 * p + 1] += f.y;
        }
    }

    const size_t row = (size_t)blockIdx.x * ROWS_PER_BLOCK + row_local;
    float4* o = reinterpret_cast<float4*>(out + row * EMBED + lane * 8);
    o[0] = make_float4(acc[0], acc[1], acc[2], acc[3]);
    o[1] = make_float4(acc[4], acc[5], acc[6], acc[7]);
}

// ---------------------------------------------------------------------------
// Launch: inputs in metadata order: content_input (int32), W (f32), b (f32)
// ---------------------------------------------------------------------------
extern "C" void kernel_launch(void* const* d_in, const int* in_sizes, int n_in,
                              void* d_out, int out_size) {
    const int*   ids  = (const int*)  d_in[0];   // [B, S, K] int32
    const float* W    = (const float*)d_in[1];   // [E, V] f32
    const float* bias = (const float*)d_in[2];   // [E] f32
    float*       out  = (float*)d_out;           // [B, S, E] f32

    transpose_W_kernel<<<VOCAB / 32, 128>>>(W);  // 3125 blocks

    const int blocks = BROWS / ROWS_PER_BLOCK;   // 1600
    gather_reduce_kernel<<<blocks, THREADS>>>(ids, bias, out);
}